// round 1
// baseline (speedup 1.0000x reference)
#include <cuda_runtime.h>
#include <math.h>

#define BB 4
#define NN 65536
#define KK 16
#define HH 64

// Scratch: xyz repacked as float4 per point (w unused). 4*65536*16B = 4 MB.
__device__ float4 g_xyz4[BB * NN];
__device__ int g_idx_is64;

// Detect whether idx buffer is int64 or int32. For int64 values < 65536,
// every odd 32-bit word (the high half) is zero. For int32 data those words
// are random indices in [0, 65536) — probability all 64 samples are zero is
// ~2^-1024. Deterministic and graph-capturable.
__global__ void detect_idx_dtype_kernel(const unsigned* __restrict__ w) {
    int ok = 1;
#pragma unroll
    for (int i = 0; i < 64; i++) {
        if (w[2 * i + 1] != 0u) ok = 0;
    }
    g_idx_is64 = ok;
}

// Repack pos (B,3,N) -> g_xyz4[b*N+n] = {x,y,z,0}. Coalesced reads per coord.
__global__ void transpose_pos_kernel(const float* __restrict__ pos) {
    int t = blockIdx.x * blockDim.x + threadIdx.x;
    if (t >= BB * NN) return;
    int b = t >> 16;
    int n = t & (NN - 1);
    const float* p = pos + (size_t)b * 3 * NN;
    float4 v;
    v.x = p[n];
    v.y = p[NN + n];
    v.z = p[2 * NN + n];
    v.w = 0.0f;
    g_xyz4[t] = v;
}

__global__ __launch_bounds__(256) void point_embed_kernel(
    const void* __restrict__ idxv,
    const float* __restrict__ dist,
    const float* __restrict__ W,
    const float* __restrict__ bias,
    float* __restrict__ out)
{
    __shared__ float4 Ws[10][16];  // W[10][64] as float4
    __shared__ float4 Bs[16];      // bias[64] as float4

    int tid = threadIdx.x;
    for (int i = tid; i < 160; i += 256)
        Ws[i >> 4][i & 15] = ((const float4*)W)[i];
    if (tid < 16) Bs[tid] = ((const float4*)bias)[tid];
    __syncthreads();

    int t = blockIdx.x * blockDim.x + tid;  // point id in [0, B*N)
    int b = t >> 16;
    int base = b << 16;

    // ---- load 16 neighbor indices (dtype-adaptive) ----
    int id[KK];
    bool is64 = (g_idx_is64 != 0);
    if (is64) {
        const int4* q = (const int4*)((const char*)idxv + (size_t)t * (KK * 8));
#pragma unroll
        for (int i = 0; i < 8; i++) {
            int4 v = q[i];
            id[2 * i + 0] = v.x & (NN - 1);
            id[2 * i + 1] = v.z & (NN - 1);
        }
    } else {
        const int4* q = (const int4*)((const char*)idxv + (size_t)t * (KK * 4));
#pragma unroll
        for (int i = 0; i < 4; i++) {
            int4 v = q[i];
            id[4 * i + 0] = v.x & (NN - 1);
            id[4 * i + 1] = v.y & (NN - 1);
            id[4 * i + 2] = v.z & (NN - 1);
            id[4 * i + 3] = v.w & (NN - 1);
        }
    }

    float4 p = g_xyz4[t];

    // ---- running maxes over K ----
    // Channels 0-2 (ext_xyz) are constant over K -> max == xyz itself.
    float mnx = -INFINITY, mny = -INFINITY, mnz = -INFINITY;
    float mdx = -INFINITY, mdy = -INFINITY, mdz = -INFINITY;
#pragma unroll
    for (int k = 0; k < KK; k++) {
        float4 q = g_xyz4[base + id[k]];  // single LDG.128 gather, L2-resident
        mnx = fmaxf(mnx, q.x);
        mny = fmaxf(mny, q.y);
        mnz = fmaxf(mnz, q.z);
        mdx = fmaxf(mdx, p.x - q.x);
        mdy = fmaxf(mdy, p.y - q.y);
        mdz = fmaxf(mdz, p.z - q.z);
    }

    const float4* d4 = (const float4*)(dist + (size_t)t * KK);
    float4 da = d4[0], db = d4[1], dc = d4[2], dd = d4[3];
    float md = fmaxf(
        fmaxf(fmaxf(fmaxf(da.x, da.y), fmaxf(da.z, da.w)),
              fmaxf(fmaxf(db.x, db.y), fmaxf(db.z, db.w))),
        fmaxf(fmaxf(fmaxf(dc.x, dc.y), fmaxf(dc.z, dc.w)),
              fmaxf(fmaxf(dd.x, dd.y), fmaxf(dd.z, dd.w))));

    float feat[10] = {p.x, p.y, p.z, mnx, mny, mnz, mdx, mdy, mdz, md};

    // ---- 10x64 matvec + bias + relu, float4-vectorized ----
    float4* o4 = (float4*)(out + (size_t)t * HH);
#pragma unroll
    for (int c = 0; c < 16; c++) {
        float4 acc = Bs[c];
#pragma unroll
        for (int j = 0; j < 10; j++) {
            float f = feat[j];
            float4 w = Ws[j][c];
            acc.x = fmaf(f, w.x, acc.x);
            acc.y = fmaf(f, w.y, acc.y);
            acc.z = fmaf(f, w.z, acc.z);
            acc.w = fmaf(f, w.w, acc.w);
        }
        acc.x = fmaxf(acc.x, 0.0f);
        acc.y = fmaxf(acc.y, 0.0f);
        acc.z = fmaxf(acc.z, 0.0f);
        acc.w = fmaxf(acc.w, 0.0f);
        o4[c] = acc;
    }
}

extern "C" void kernel_launch(void* const* d_in, const int* in_sizes, int n_in,
                              void* d_out, int out_size) {
    const float* pos  = (const float*)d_in[0];
    const void*  idx  = d_in[1];
    const float* dist = (const float*)d_in[2];
    const float* W    = (const float*)d_in[3];
    const float* bias = (const float*)d_in[4];
    float* out = (float*)d_out;

    detect_idx_dtype_kernel<<<1, 1>>>((const unsigned*)idx);
    transpose_pos_kernel<<<(BB * NN + 255) / 256, 256>>>(pos);
    point_embed_kernel<<<(BB * NN) / 256, 256>>>(idx, dist, W, bias, out);
}

// round 4
// speedup vs baseline: 1.4003x; 1.4003x over previous
#include <cuda_runtime.h>
#include <math.h>

#define BB 4
#define NN 65536
#define KK 16
#define HH 64
#define TPB 256

// Scratch: xyz repacked as float4 per point (w unused). 4*65536*16B = 4 MB.
__device__ float4 g_xyz4[BB * NN];
__device__ int g_idx_is64;

// Transpose pos (B,3,N) -> g_xyz4[b*N+n] = {x,y,z,0}, coalesced per coord.
// Warp 0 of block 0 additionally detects idx dtype: for int64 values < 65536
// every odd 32-bit word is zero; for int32 those words are random indices
// (P[all 64 zero] ~ 2^-1024). Deterministic, graph-capturable, no extra launch.
__global__ void transpose_pos_kernel(const float* __restrict__ pos,
                                     const unsigned* __restrict__ idxw) {
    if (blockIdx.x == 0 && threadIdx.x < 32) {
        unsigned v = idxw[4 * threadIdx.x + 1] | idxw[4 * threadIdx.x + 3];
        unsigned any = __ballot_sync(0xffffffffu, v != 0u);
        if (threadIdx.x == 0) g_idx_is64 = (any == 0u) ? 1 : 0;
    }
    int t = blockIdx.x * blockDim.x + threadIdx.x;
    if (t >= BB * NN) return;
    int b = t >> 16;
    int n = t & (NN - 1);
    const float* p = pos + (size_t)b * 3 * NN;
    float4 v;
    v.x = p[n];
    v.y = p[NN + n];
    v.z = p[2 * NN + n];
    v.w = 0.0f;
    g_xyz4[t] = v;
}

__global__ __launch_bounds__(TPB) void point_embed_kernel(
    const void* __restrict__ idxv,
    const float* __restrict__ dist,
    const float* __restrict__ W,
    const float* __restrict__ bias,
    float* __restrict__ out)
{
    __shared__ float feat_s[TPB][10];

    int tid = threadIdx.x;
    int t = blockIdx.x * TPB + tid;   // this thread's point (phase 1)
    int b = t >> 16;
    int base = b << 16;

    // ---------- Phase 1: per-point feature computation ----------
    int id[KK];
    if (g_idx_is64 != 0) {
        const int4* q = (const int4*)((const char*)idxv + (size_t)t * (KK * 8));
#pragma unroll
        for (int i = 0; i < 8; i++) {
            int4 v = q[i];
            id[2 * i + 0] = v.x & (NN - 1);
            id[2 * i + 1] = v.z & (NN - 1);
        }
    } else {
        const int4* q = (const int4*)((const char*)idxv + (size_t)t * (KK * 4));
#pragma unroll
        for (int i = 0; i < 4; i++) {
            int4 v = q[i];
            id[4 * i + 0] = v.x & (NN - 1);
            id[4 * i + 1] = v.y & (NN - 1);
            id[4 * i + 2] = v.z & (NN - 1);
            id[4 * i + 3] = v.w & (NN - 1);
        }
    }

    float4 p = g_xyz4[t];

    float mnx = -INFINITY, mny = -INFINITY, mnz = -INFINITY;
    float mdx = -INFINITY, mdy = -INFINITY, mdz = -INFINITY;
#pragma unroll
    for (int k = 0; k < KK; k++) {
        float4 q = g_xyz4[base + id[k]];  // one LDG.128 per neighbor, L2-resident
        mnx = fmaxf(mnx, q.x);
        mny = fmaxf(mny, q.y);
        mnz = fmaxf(mnz, q.z);
        mdx = fmaxf(mdx, p.x - q.x);
        mdy = fmaxf(mdy, p.y - q.y);
        mdz = fmaxf(mdz, p.z - q.z);
    }

    const float4* d4 = (const float4*)(dist + (size_t)t * KK);
    float4 da = d4[0], db = d4[1], dc = d4[2], dd = d4[3];
    float md = fmaxf(
        fmaxf(fmaxf(fmaxf(da.x, da.y), fmaxf(da.z, da.w)),
              fmaxf(fmaxf(db.x, db.y), fmaxf(db.z, db.w))),
        fmaxf(fmaxf(fmaxf(dc.x, dc.y), fmaxf(dc.z, dc.w)),
              fmaxf(fmaxf(dd.x, dd.y), fmaxf(dd.z, dd.w))));

    feat_s[tid][0] = p.x;  feat_s[tid][1] = p.y;  feat_s[tid][2] = p.z;
    feat_s[tid][3] = mnx;  feat_s[tid][4] = mny;  feat_s[tid][5] = mnz;
    feat_s[tid][6] = mdx;  feat_s[tid][7] = mdy;  feat_s[tid][8] = mdz;
    feat_s[tid][9] = md;

    // Channel group is FIXED per thread (256 % 16 == 0): hoist W columns.
    int c = tid & 15;                       // which float4 of the 64 outputs
    float4 Wc[10];
#pragma unroll
    for (int j = 0; j < 10; j++)
        Wc[j] = ((const float4*)W)[j * 16 + c];
    float4 Bc = ((const float4*)bias)[c];

    __syncthreads();

    // ---------- Phase 2: matvec + relu with coalesced stores ----------
    // Warp lanes 0-15 -> point pl channels, lanes 16-31 -> point pl+1:
    // each warp stores 512B contiguous (4 L1 wavefronts vs 32 before).
    int sub = tid >> 4;                     // 0..15: which point within group
    long blk_base = (long)blockIdx.x * TPB;
#pragma unroll
    for (int it = 0; it < 16; it++) {
        int pl = it * 16 + sub;             // local point index 0..255
        float f[10];
#pragma unroll
        for (int j = 0; j < 10; j++) f[j] = feat_s[pl][j];  // broadcast LDS

        float4 acc = Bc;
#pragma unroll
        for (int j = 0; j < 10; j++) {
            acc.x = fmaf(f[j], Wc[j].x, acc.x);
            acc.y = fmaf(f[j], Wc[j].y, acc.y);
            acc.z = fmaf(f[j], Wc[j].z, acc.z);
            acc.w = fmaf(f[j], Wc[j].w, acc.w);
        }
        acc.x = fmaxf(acc.x, 0.0f);
        acc.y = fmaxf(acc.y, 0.0f);
        acc.z = fmaxf(acc.z, 0.0f);
        acc.w = fmaxf(acc.w, 0.0f);

        ((float4*)(out + (blk_base + pl) * HH))[c] = acc;
    }
}

extern "C" void kernel_launch(void* const* d_in, const int* in_sizes, int n_in,
                              void* d_out, int out_size) {
    const float* pos  = (const float*)d_in[0];
    const void*  idx  = d_in[1];
    const float* dist = (const float*)d_in[2];
    const float* W    = (const float*)d_in[3];
    const float* bias = (const float*)d_in[4];
    float* out = (float*)d_out;

    transpose_pos_kernel<<<(BB * NN + TPB - 1) / TPB, TPB>>>(pos, (const unsigned*)idx);
    point_embed_kernel<<<(BB * NN) / TPB, TPB>>>(idx, dist, W, bias, out);
}